// round 6
// baseline (speedup 1.0000x reference)
#include <cuda_runtime.h>
#include <cuda_bf16.h>

// RippleNet restructure: (R h).item == (R^T item).h -> q[r] = R[r]^T item per b
// (32 relations), so each memory's logit is a 16-dot, computed PRIVATELY per
// lane (lane owns memory) -> no reduce shuffles, no index shuffles.
//
// H=2, B=2048, M=64, D=16, N_ENT=500000, N_REL=32.
// ent_emb (32MB) is L2-resident across graph replays -> gathers are L2 hits.
// Grid: 2048 blocks x 128 thr; warp = (hop, half): 32 memories per warp.

#define NUM_B   2048
#define NUM_M   64
#define DIM     16
#define NUM_REL 32
#define QPAD    20      // padded q row (floats): spreads LDS banks over r mod 8
#define THREADS 128

__global__ __launch_bounds__(THREADS, 12)
void ripplenet_kernel(const int*   __restrict__ items,
                      const int*   __restrict__ heads,
                      const int*   __restrict__ rels,
                      const int*   __restrict__ tails,
                      const float* __restrict__ ent,
                      const float* __restrict__ rel,
                      float*       __restrict__ out)
{
    __shared__ __align__(16) float q_sh[NUM_REL][QPAD];  // q[r] = R[r]^T item
    __shared__ float item_sh[DIM];
    __shared__ float logit_sh[2][NUM_M];
    __shared__ float prob_sh[2][NUM_M];
    __shared__ int   tidx_sh[4][32];
    __shared__ float user_sh[4][DIM];

    const int tid  = threadIdx.x;
    const int warp = tid >> 5;
    const int lane = tid & 31;
    const int hop  = warp & 1;     // which hop this warp handles
    const int half = warp >> 1;    // which 32-memory half
    const int b    = blockIdx.x;
    const int grp  = lane >> 4;    // half-warp id for tail pass
    const int li   = lane & 15;    // dim index

    // ---- item embedding -> shared ----
    if (tid < DIM) item_sh[tid] = ent[(size_t)items[b] * DIM + tid];
    __syncthreads();

    // ---- q[r][i] = sum_j rel[r][j][i] * item[j]; 128 thr: (r mod 8, i) ----
    {
        const int i  = tid & 15;
        const int r0 = tid >> 4;                  // 0..7
        #pragma unroll
        for (int k = 0; k < 4; ++k) {
            const int r = r0 + 8 * k;
            const float* Rr = rel + r * DIM * DIM;
            float a0 = 0.f, a1 = 0.f, a2 = 0.f, a3 = 0.f;
            #pragma unroll
            for (int j = 0; j < DIM; j += 4) {    // coalesced per 16-thr group
                a0 = fmaf(Rr[(j + 0) * DIM + i], item_sh[j + 0], a0);
                a1 = fmaf(Rr[(j + 1) * DIM + i], item_sh[j + 1], a1);
                a2 = fmaf(Rr[(j + 2) * DIM + i], item_sh[j + 2], a2);
                a3 = fmaf(Rr[(j + 3) * DIM + i], item_sh[j + 3], a3);
            }
            q_sh[r][i] = (a0 + a1) + (a2 + a3);
        }
    }

    // ---- per-lane memory: coalesced index loads (lane's own memory) ----
    const int m    = half * 32 + lane;
    const int base = (hop * NUM_B + b) * NUM_M + m;
    const int hidx = heads[base];
    const int ridx = rels[base];
    tidx_sh[warp][lane] = tails[base];
    __syncthreads();                 // publishes q_sh (and tidx_sh)

    // ---- logit: private 16-dot, no shuffles. 4x LDG.128 + 4x LDS.128 ----
    {
        const float4* hp = (const float4*)(ent + (size_t)hidx * DIM);
        const float4  h0 = hp[0], h1 = hp[1], h2 = hp[2], h3 = hp[3];
        const float4* qp = (const float4*)(&q_sh[ridx][0]);
        const float4  q0 = qp[0], q1 = qp[1], q2 = qp[2], q3 = qp[3];
        float d0 = h0.x * q0.x + h0.y * q0.y + h0.z * q0.z + h0.w * q0.w;
        float d1 = h1.x * q1.x + h1.y * q1.y + h1.z * q1.z + h1.w * q1.w;
        float d2 = h2.x * q2.x + h2.y * q2.y + h2.z * q2.z + h2.w * q2.w;
        float d3 = h3.x * q3.x + h3.y * q3.y + h3.z * q3.z + h3.w * q3.w;
        logit_sh[hop][m] = (d0 + d1) + (d2 + d3);
    }
    __syncthreads();                 // both halves' logits visible

    // ---- softmax over M=64 (both warps of a hop compute identically) ----
    {
        const float l0 = logit_sh[hop][lane];
        const float l1 = logit_sh[hop][lane + 32];
        float mx = fmaxf(l0, l1);
        #pragma unroll
        for (int o = 16; o >= 1; o >>= 1)
            mx = fmaxf(mx, __shfl_xor_sync(0xffffffffu, mx, o));
        const float e0 = __expf(l0 - mx), e1 = __expf(l1 - mx);
        float s = e0 + e1;
        #pragma unroll
        for (int o = 16; o >= 1; o >>= 1)
            s += __shfl_xor_sync(0xffffffffu, s, o);
        const float inv = __frcp_rn(s);
        prob_sh[hop][lane]      = e0 * inv;   // redundant identical writes
        prob_sh[hop][lane + 32] = e1 * inv;   // from both warps of the hop
    }
    __syncwarp();                    // warp reads only values it wrote itself

    // ---- tail aggregation: half-warp per memory, coalesced 64B gathers ----
    float acc = 0.f;
    #pragma unroll
    for (int t = 0; t < 16; ++t) {
        const int mm  = half * 32 + 2 * t + grp;
        const int tix = tidx_sh[warp][2 * t + grp];      // LDS broadcast
        acc = fmaf(prob_sh[hop][mm], ent[(size_t)tix * DIM + li], acc);
    }
    acc += __shfl_xor_sync(0xffffffffu, acc, 16);        // merge half-warps
    if (lane < DIM) user_sh[warp][lane] = acc;
    __syncthreads();

    // ---- combine 4 partials, dot with item, sigmoid ----
    if (warp == 0) {
        const float ur = user_sh[0][li] + user_sh[1][li]
                       + user_sh[2][li] + user_sh[3][li];
        float d = ur * item_sh[li];
        #pragma unroll
        for (int o = 8; o >= 1; o >>= 1)
            d += __shfl_xor_sync(0xffffffffu, d, o, 16);
        if (lane == 0) out[b] = __frcp_rn(1.f + __expf(-d));
    }
}

extern "C" void kernel_launch(void* const* d_in, const int* in_sizes, int n_in,
                              void* d_out, int out_size)
{
    const int*   items = (const int*)  d_in[0];
    const int*   heads = (const int*)  d_in[1];
    const int*   rels  = (const int*)  d_in[2];
    const int*   tails = (const int*)  d_in[3];
    const float* ent   = (const float*)d_in[4];
    const float* rel   = (const float*)d_in[5];
    float*       out   = (float*)d_out;

    ripplenet_kernel<<<NUM_B, THREADS>>>(items, heads, rels, tails, ent, rel, out);
}

// round 11
// speedup vs baseline: 1.3646x; 1.3646x over previous
#include <cuda_runtime.h>
#include <cuda_bf16.h>

// RippleNet: (R h).item == (R^T item).h -> q[r] = R[r]^T item per b (32 rels),
// each memory's logit is a 16-dot.
// Gather layout: 4 lanes per 64B entity row (float4 each) -> 64B/wavefront.
// BOTH head and tail rows are prefetched into registers before the q-build
// barrier, so all gather latency overlaps the q FMAs + barrier.
//
// H=2, B=2048, M=64, D=16, N_ENT=500000, N_REL=32.
// Block = 128 thr = 4 warps = (hop, half): 32 memories per warp. Grid = 2048.

#define NUM_B   2048
#define NUM_M   64
#define DIM     16
#define NUM_REL 32
#define QPAD    20      // 80B rows: 16B-aligned, start banks cycle mod 32
#define THREADS 128

__global__ __launch_bounds__(THREADS, 6)
void ripplenet_kernel(const int*   __restrict__ items,
                      const int*   __restrict__ heads,
                      const int*   __restrict__ rels,
                      const int*   __restrict__ tails,
                      const float* __restrict__ ent,
                      const float* __restrict__ rel,
                      float*       __restrict__ out)
{
    __shared__ __align__(16) float q_sh[NUM_REL][QPAD];  // q[r] = R[r]^T item
    __shared__ float logit_sh[2][NUM_M];
    __shared__ float user_sh[4][DIM];

    const int tid  = threadIdx.x;
    const int warp = tid >> 5;
    const int lane = tid & 31;
    const int hop  = warp >> 1;     // 0/1
    const int half = warp & 1;      // which 32-memory half
    const int b    = blockIdx.x;
    const int g    = lane >> 2;     // row group 0..7
    const int c    = lane & 3;      // float4 chunk within row

    const float4* ent4 = (const float4*)ent;
    const unsigned FULL = 0xffffffffu;

    // ---- indices: coalesced, lane owns memory (half*32 + lane) ----
    const int base = (hop * NUM_B + b) * NUM_M + half * 32 + lane;
    const int tidx = tails[base];
    const int hidx = heads[base];
    const int ridx = rels[base];

    // ---- PREFETCH head + tail rows: 4 lanes per row, rows k*8+g ----
    // 8 independent LDG.128 per lane in flight through the q-build phase.
    int hr[4];
    #pragma unroll
    for (int k = 0; k < 4; ++k)
        hr[k] = __shfl_sync(FULL, hidx, k * 8 + g);

    float4 hv[4], tv[4];
    #pragma unroll
    for (int k = 0; k < 4; ++k) {
        const int tr = __shfl_sync(FULL, tidx, k * 8 + g);
        hv[k] = ent4[(size_t)hr[k] * 4 + c];
        tv[k] = ent4[(size_t)tr    * 4 + c];
    }

    // ---- item embedding: uniform broadcast loads into registers ----
    const int it = items[b];
    float itf[16];
    {
        float4 i0 = ent4[(size_t)it * 4 + 0];
        float4 i1 = ent4[(size_t)it * 4 + 1];
        float4 i2 = ent4[(size_t)it * 4 + 2];
        float4 i3 = ent4[(size_t)it * 4 + 3];
        *(float4*)&itf[0]  = i0; *(float4*)&itf[4]  = i1;
        *(float4*)&itf[8]  = i2; *(float4*)&itf[12] = i3;
    }

    // ---- q[r][i] = sum_j rel[r][j][i] * item[j]; 128 thr -> 4 r's each ----
    // These FMAs + the barrier overlap the 8 in-flight gathers above.
    {
        const int i  = tid & 15;
        const int r0 = tid >> 4;                   // 0..7
        #pragma unroll
        for (int k = 0; k < 4; ++k) {
            const int r = r0 + 8 * k;
            const float* Rr = rel + r * DIM * DIM;
            float a0 = 0.f, a1 = 0.f;
            #pragma unroll
            for (int j = 0; j < DIM; j += 2) {     // coalesced per 16-thr group
                a0 = fmaf(Rr[(j + 0) * DIM + i], itf[j + 0], a0);
                a1 = fmaf(Rr[(j + 1) * DIM + i], itf[j + 1], a1);
            }
            q_sh[r][i] = a0 + a1;
        }
    }
    __syncthreads();                  // q_sh ready

    // ---- logits from prefetched head registers + q_sh, quad reduce ----
    #pragma unroll
    for (int k = 0; k < 4; ++k) {
        const int src = k * 8 + g;
        const int rr  = __shfl_sync(FULL, ridx, src);
        const float4 qv = *(const float4*)&q_sh[rr][4 * c];
        float p = hv[k].x * qv.x + hv[k].y * qv.y
                + hv[k].z * qv.z + hv[k].w * qv.w;
        p += __shfl_xor_sync(FULL, p, 1);
        p += __shfl_xor_sync(FULL, p, 2);
        if (c == 0) logit_sh[hop][half * 32 + src] = p;
    }
    __syncthreads();                  // both halves' logits visible

    // ---- softmax over M=64 (redundant in both warps of the hop) ----
    // logits are O(0.1): skip max-subtraction, exp exact here.
    const float l0 = logit_sh[hop][lane];
    const float l1 = logit_sh[hop][lane + 32];
    const float e0 = __expf(l0), e1 = __expf(l1);
    float s = e0 + e1;
    #pragma unroll
    for (int o = 16; o >= 1; o >>= 1)
        s += __shfl_xor_sync(FULL, s, o);
    const float inv = __frcp_rn(s);
    const float myp = (half == 0 ? e0 : e1) * inv;  // prob of memory half*32+lane

    // ---- tail accumulate on prefetched registers ----
    float4 acc = make_float4(0.f, 0.f, 0.f, 0.f);
    #pragma unroll
    for (int k = 0; k < 4; ++k) {
        const float p = __shfl_sync(FULL, myp, k * 8 + g);
        acc.x = fmaf(p, tv[k].x, acc.x);
        acc.y = fmaf(p, tv[k].y, acc.y);
        acc.z = fmaf(p, tv[k].z, acc.z);
        acc.w = fmaf(p, tv[k].w, acc.w);
    }
    #pragma unroll
    for (int o = 4; o <= 16; o <<= 1) {            // combine the 8 row-groups
        acc.x += __shfl_xor_sync(FULL, acc.x, o);
        acc.y += __shfl_xor_sync(FULL, acc.y, o);
        acc.z += __shfl_xor_sync(FULL, acc.z, o);
        acc.w += __shfl_xor_sync(FULL, acc.w, o);
    }
    if (lane < 4) *(float4*)&user_sh[warp][4 * lane] = acc;  // lane holds chunk c=lane
    __syncthreads();

    // ---- combine 4 warp partials, dot with item, sigmoid ----
    if (warp == 0 && lane < DIM) {
        const float ur = user_sh[0][lane] + user_sh[1][lane]
                       + user_sh[2][lane] + user_sh[3][lane];
        float d = ur * ent[(size_t)it * DIM + lane];   // L1-hit by now
        #pragma unroll
        for (int o = 8; o >= 1; o >>= 1)
            d += __shfl_xor_sync(0x0000ffffu, d, o, 16);
        if (lane == 0) out[b] = __frcp_rn(1.f + __expf(-d));
    }
}

extern "C" void kernel_launch(void* const* d_in, const int* in_sizes, int n_in,
                              void* d_out, int out_size)
{
    const int*   items = (const int*)  d_in[0];
    const int*   heads = (const int*)  d_in[1];
    const int*   rels  = (const int*)  d_in[2];
    const int*   tails = (const int*)  d_in[3];
    const float* ent   = (const float*)d_in[4];
    const float* rel   = (const float*)d_in[5];
    float*       out   = (float*)d_out;

    ripplenet_kernel<<<NUM_B, THREADS>>>(items, heads, rels, tails, ent, rel, out);
}

// round 13
// speedup vs baseline: 1.3907x; 1.0191x over previous
#include <cuda_runtime.h>
#include <cuda_bf16.h>

// RippleNet: (R h).item == (R^T item).h -> q[r] = R[r]^T item per b (32 rels),
// each memory's logit is a 16-dot.
// Gather layout: 4 lanes per 64B entity row (float4 each) -> 64B/wavefront.
// Head + tail rows prefetched into registers before the q-build barrier so all
// gather latency overlaps the q FMAs + barrier. Item kept in SHARED (not regs)
// to hold regs <= 64 -> 8 blocks/SM occupancy.
//
// H=2, B=2048, M=64, D=16, N_ENT=500000, N_REL=32.
// Block = 128 thr = 4 warps = (hop, half): 32 memories per warp. Grid = 2048.

#define NUM_B   2048
#define NUM_M   64
#define DIM     16
#define NUM_REL 32
#define QPAD    20      // 80B rows: 16B-aligned
#define THREADS 128

__global__ __launch_bounds__(THREADS, 8)
void ripplenet_kernel(const int*   __restrict__ items,
                      const int*   __restrict__ heads,
                      const int*   __restrict__ rels,
                      const int*   __restrict__ tails,
                      const float* __restrict__ ent,
                      const float* __restrict__ rel,
                      float*       __restrict__ out)
{
    __shared__ __align__(16) float q_sh[NUM_REL][QPAD];  // q[r] = R[r]^T item
    __shared__ __align__(16) float item_sh[DIM];
    __shared__ float logit_sh[2][NUM_M];
    __shared__ float user_sh[4][DIM];

    const int tid  = threadIdx.x;
    const int warp = tid >> 5;
    const int lane = tid & 31;
    const int hop  = warp >> 1;     // 0/1
    const int half = warp & 1;      // which 32-memory half
    const int b    = blockIdx.x;
    const int g    = lane >> 2;     // row group 0..7
    const int c    = lane & 3;      // float4 chunk within row

    const float4* ent4 = (const float4*)ent;
    const unsigned FULL = 0xffffffffu;

    // ---- indices: coalesced, lane owns memory (half*32 + lane) ----
    const int base = (hop * NUM_B + b) * NUM_M + half * 32 + lane;
    const int tidx = tails[base];
    const int hidx = heads[base];
    const int ridx = rels[base];

    // ---- item embedding -> shared (warp 0, 4 lanes x float4) ----
    if (warp == 0 && lane < 4) {
        const int it = items[b];
        ((float4*)item_sh)[lane] = ent4[(size_t)it * 4 + lane];
    }

    // ---- distribute row indices first, then front-batch all 8 LDG.128 ----
    int hr[4], tr[4];
    #pragma unroll
    for (int k = 0; k < 4; ++k) {
        hr[k] = __shfl_sync(FULL, hidx, k * 8 + g);
        tr[k] = __shfl_sync(FULL, tidx, k * 8 + g);
    }
    float4 hv[4], tv[4];
    #pragma unroll
    for (int k = 0; k < 4; ++k) {
        hv[k] = ent4[(size_t)hr[k] * 4 + c];
        tv[k] = ent4[(size_t)tr[k] * 4 + c];
    }

    __syncthreads();                  // item_sh ready

    // ---- q[r][i] = sum_j rel[r][j][i] * item[j]; 128 thr -> 4 r's each ----
    // FMAs + barriers overlap the 8 in-flight gathers above.
    {
        const int i  = tid & 15;
        const int r0 = tid >> 4;                   // 0..7
        #pragma unroll
        for (int k = 0; k < 4; ++k) {
            const int r = r0 + 8 * k;
            const float* Rr = rel + r * DIM * DIM;
            float a0 = 0.f, a1 = 0.f;
            #pragma unroll
            for (int j = 0; j < DIM; j += 2) {     // item_sh[j]: broadcast LDS
                a0 = fmaf(Rr[(j + 0) * DIM + i], item_sh[j + 0], a0);
                a1 = fmaf(Rr[(j + 1) * DIM + i], item_sh[j + 1], a1);
            }
            q_sh[r][i] = a0 + a1;
        }
    }
    __syncthreads();                  // q_sh ready

    // ---- logits from prefetched head registers + q_sh, quad reduce ----
    #pragma unroll
    for (int k = 0; k < 4; ++k) {
        const int src = k * 8 + g;
        const int rr  = __shfl_sync(FULL, ridx, src);
        const float4 qv = *(const float4*)&q_sh[rr][4 * c];
        float p = hv[k].x * qv.x + hv[k].y * qv.y
                + hv[k].z * qv.z + hv[k].w * qv.w;
        p += __shfl_xor_sync(FULL, p, 1);
        p += __shfl_xor_sync(FULL, p, 2);
        if (c == 0) logit_sh[hop][half * 32 + src] = p;
    }
    __syncthreads();                  // both halves' logits visible

    // ---- softmax over M=64 (redundant in both warps of the hop) ----
    // logits are O(0.1): skip max-subtraction, exp exact here.
    const float l0 = logit_sh[hop][lane];
    const float l1 = logit_sh[hop][lane + 32];
    const float e0 = __expf(l0), e1 = __expf(l1);
    float s = e0 + e1;
    #pragma unroll
    for (int o = 16; o >= 1; o >>= 1)
        s += __shfl_xor_sync(FULL, s, o);
    const float inv = __frcp_rn(s);
    const float myp = (half == 0 ? e0 : e1) * inv;  // prob of memory half*32+lane

    // ---- tail accumulate on prefetched registers ----
    float4 acc = make_float4(0.f, 0.f, 0.f, 0.f);
    #pragma unroll
    for (int k = 0; k < 4; ++k) {
        const float p = __shfl_sync(FULL, myp, k * 8 + g);
        acc.x = fmaf(p, tv[k].x, acc.x);
        acc.y = fmaf(p, tv[k].y, acc.y);
        acc.z = fmaf(p, tv[k].z, acc.z);
        acc.w = fmaf(p, tv[k].w, acc.w);
    }
    #pragma unroll
    for (int o = 4; o <= 16; o <<= 1) {            // combine the 8 row-groups
        acc.x += __shfl_xor_sync(FULL, acc.x, o);
        acc.y += __shfl_xor_sync(FULL, acc.y, o);
        acc.z += __shfl_xor_sync(FULL, acc.z, o);
        acc.w += __shfl_xor_sync(FULL, acc.w, o);
    }
    if (lane < 4) *(float4*)&user_sh[warp][4 * lane] = acc;  // lane holds chunk c=lane
    __syncthreads();

    // ---- combine 4 warp partials, dot with item, sigmoid ----
    if (warp == 0 && lane < DIM) {
        const float ur = user_sh[0][lane] + user_sh[1][lane]
                       + user_sh[2][lane] + user_sh[3][lane];
        float d = ur * item_sh[lane];
        #pragma unroll
        for (int o = 8; o >= 1; o >>= 1)
            d += __shfl_xor_sync(0x0000ffffu, d, o, 16);
        if (lane == 0) out[b] = __frcp_rn(1.f + __expf(-d));
    }
}

extern "C" void kernel_launch(void* const* d_in, const int* in_sizes, int n_in,
                              void* d_out, int out_size)
{
    const int*   items = (const int*)  d_in[0];
    const int*   heads = (const int*)  d_in[1];
    const int*   rels  = (const int*)  d_in[2];
    const int*   tails = (const int*)  d_in[3];
    const float* ent   = (const float*)d_in[4];
    const float* rel   = (const float*)d_in[5];
    float*       out   = (float*)d_out;

    ripplenet_kernel<<<NUM_B, THREADS>>>(items, heads, rels, tails, ent, rel, out);
}